// round 6
// baseline (speedup 1.0000x reference)
#include <cuda_runtime.h>

#define L_SEQ   4096
#define DMODEL  1024

__device__ float g_Q [L_SEQ * DMODEL];
__device__ float g_Kt[DMODEL * L_SEQ];   // K projection TRANSPOSED [d][l]
__device__ float g_V [L_SEQ * DMODEL];
__device__ float g_A [L_SEQ * DMODEL];

__device__ __forceinline__ void fma2(float2& d, const float2 a, const float2 b) {
    unsigned long long& dd = reinterpret_cast<unsigned long long&>(d);
    const unsigned long long aa = *reinterpret_cast<const unsigned long long*>(&a);
    const unsigned long long bb = *reinterpret_cast<const unsigned long long*>(&b);
    asm("fma.rn.f32x2 %0, %1, %2, %0;" : "+l"(dd) : "l"(aa), "l"(bb));
}

// ---------------- GEMM: Y = X(MxK) * W^T(NxK); transOut=1 -> Y[n][m] ----------------
__global__ __launch_bounds__(256)
void gemm_xwt(const float* __restrict__ X, const float* __restrict__ W,
              float* __restrict__ Y, int M, int N, int K, int transOut)
{
    __shared__ float As [16][132];   // As[k][m]
    __shared__ float Bsd[16][132];   // Bsd[k][2n] value-duplicated

    const int t  = threadIdx.x;
    const int mb = blockIdx.y * 128;
    const int nb = blockIdx.x * 64;
    const int lr = t >> 2, kg = t & 3;
    const int tx = t & 15, ty = t >> 4;

    const float* xA0 = X + (size_t)(mb + lr)      * K + kg * 4;
    const float* xA1 = X + (size_t)(mb + lr + 64) * K + kg * 4;
    const float* xB  = W + (size_t)(nb + lr)      * K + kg * 4;

    float2 acc[4][4];
    #pragma unroll
    for (int i = 0; i < 4; i++)
        #pragma unroll
        for (int j = 0; j < 4; j++) acc[i][j] = make_float2(0.f, 0.f);

    const int nt = K / 16;
    float4 pa0 = *(const float4*)xA0;
    float4 pa1 = *(const float4*)xA1;
    float4 pb  = *(const float4*)xB;

    for (int kt = 0; kt < nt; kt++) {
        __syncthreads();
        As[kg*4+0][lr]    = pa0.x; As[kg*4+1][lr]    = pa0.y;
        As[kg*4+2][lr]    = pa0.z; As[kg*4+3][lr]    = pa0.w;
        As[kg*4+0][lr+64] = pa1.x; As[kg*4+1][lr+64] = pa1.y;
        As[kg*4+2][lr+64] = pa1.z; As[kg*4+3][lr+64] = pa1.w;
        *(float2*)&Bsd[kg*4+0][2*lr] = make_float2(pb.x, pb.x);
        *(float2*)&Bsd[kg*4+1][2*lr] = make_float2(pb.y, pb.y);
        *(float2*)&Bsd[kg*4+2][2*lr] = make_float2(pb.z, pb.z);
        *(float2*)&Bsd[kg*4+3][2*lr] = make_float2(pb.w, pb.w);
        __syncthreads();
        if (kt + 1 < nt) {
            pa0 = *(const float4*)(xA0 + (kt + 1) * 16);
            pa1 = *(const float4*)(xA1 + (kt + 1) * 16);
            pb  = *(const float4*)(xB  + (kt + 1) * 16);
        }
        #pragma unroll
        for (int k = 0; k < 16; k++) {
            float4 a0 = *(const float4*)&As[k][ty*8];
            float4 a1 = *(const float4*)&As[k][ty*8 + 4];
            float2 ap0 = make_float2(a0.x, a0.y), ap1 = make_float2(a0.z, a0.w);
            float2 ap2 = make_float2(a1.x, a1.y), ap3 = make_float2(a1.z, a1.w);
            #pragma unroll
            for (int j = 0; j < 4; j++) {
                float2 b = *(const float2*)&Bsd[k][(tx*4 + j) * 2];
                fma2(acc[0][j], ap0, b);
                fma2(acc[1][j], ap1, b);
                fma2(acc[2][j], ap2, b);
                fma2(acc[3][j], ap3, b);
            }
        }
    }

    if (!transOut) {
        #pragma unroll
        for (int ip = 0; ip < 4; ip++) {
            int m0 = mb + ty*8 + 2*ip;
            *(float4*)&Y[(size_t)m0     * N + nb + tx*4] =
                make_float4(acc[ip][0].x, acc[ip][1].x, acc[ip][2].x, acc[ip][3].x);
            *(float4*)&Y[(size_t)(m0+1) * N + nb + tx*4] =
                make_float4(acc[ip][0].y, acc[ip][1].y, acc[ip][2].y, acc[ip][3].y);
        }
    } else {
        #pragma unroll
        for (int j = 0; j < 4; j++) {
            int n = nb + tx*4 + j;
            *(float4*)&Y[(size_t)n * M + mb + ty*8] =
                make_float4(acc[0][j].x, acc[0][j].y, acc[1][j].x, acc[1][j].y);
            *(float4*)&Y[(size_t)n * M + mb + ty*8 + 4] =
                make_float4(acc[2][j].x, acc[2][j].y, acc[3][j].x, acc[3][j].y);
        }
    }
}

// ---------------- Flash attention (fp32, online softmax) ----------------
#define ATT_SMEM ((64*68 + 64*132 + 64*68 + 64*132) * 4)

__global__ __launch_bounds__(128)
void attn_kernel(const float* __restrict__ Qp, const float* __restrict__ Kt,
                 const float* __restrict__ Vp, float* __restrict__ Aout)
{
    extern __shared__ float sm[];
    float* Qst = sm;                 // [64][68] Q^T : [d][r]
    float* Ksd = sm + 64*68;         // [64][132] K dup : [d][2c]
    float* Vs  = Ksd + 64*132;       // [64][68]  V : [j][dd]
    float* Psd = Vs + 64*68;         // [64][132] P dup : [r][2j]

    const int t  = threadIdx.x;
    const int h  = blockIdx.y;
    const int q0 = blockIdx.x * 64;
    const int tx = t & 15, ty = t >> 4;   // ty 0..7

    #pragma unroll
    for (int it = 0; it < 8; it++) {
        int r = ty + it*8, d0 = tx*4;
        float4 v = *(const float4*)&Qp[(size_t)(q0 + r) * DMODEL + h*64 + d0];
        Qst[(d0+0)*68 + r] = v.x; Qst[(d0+1)*68 + r] = v.y;
        Qst[(d0+2)*68 + r] = v.z; Qst[(d0+3)*68 + r] = v.w;
    }

    float2 o2[8][2];
    float  m_r[8], l_r[8];
    #pragma unroll
    for (int i = 0; i < 8; i++) {
        o2[i][0] = make_float2(0.f, 0.f); o2[i][1] = make_float2(0.f, 0.f);
        m_r[i] = -1e30f; l_r[i] = 0.f;
    }
    __syncthreads();

    for (int c0 = 0; c0 < L_SEQ; c0 += 64) {
        #pragma unroll
        for (int it = 0; it < 8; it++) {
            int d = ty + it*8, c4 = tx*4;
            float4 v = *(const float4*)&Kt[(size_t)(h*64 + d) * L_SEQ + c0 + c4];
            float* p = &Ksd[d*132 + 2*c4];
            ((float4*)p)[0] = make_float4(v.x, v.x, v.y, v.y);
            ((float4*)p)[1] = make_float4(v.z, v.z, v.w, v.w);
            float4 w = *(const float4*)&Vp[(size_t)(c0 + d) * DMODEL + h*64 + c4];
            *(float4*)&Vs[d*68 + c4] = w;
        }
        __syncthreads();

        float2 s2[4][4];
        #pragma unroll
        for (int i = 0; i < 4; i++)
            #pragma unroll
            for (int j = 0; j < 4; j++) s2[i][j] = make_float2(0.f, 0.f);

        #pragma unroll 4
        for (int d = 0; d < 64; d++) {
            float4 a0 = *(const float4*)&Qst[d*68 + ty*8];
            float4 a1 = *(const float4*)&Qst[d*68 + ty*8 + 4];
            float2 ap0 = make_float2(a0.x, a0.y), ap1 = make_float2(a0.z, a0.w);
            float2 ap2 = make_float2(a1.x, a1.y), ap3 = make_float2(a1.z, a1.w);
            #pragma unroll
            for (int j = 0; j < 4; j++) {
                float2 b = *(const float2*)&Ksd[d*132 + (tx*4 + j) * 2];
                fma2(s2[0][j], ap0, b);
                fma2(s2[1][j], ap1, b);
                fma2(s2[2][j], ap2, b);
                fma2(s2[3][j], ap3, b);
            }
        }

        #pragma unroll
        for (int ip = 0; ip < 4; ip++) {
            float ma = -1e30f, mb = -1e30f;
            #pragma unroll
            for (int j = 0; j < 4; j++) {
                s2[ip][j].x *= 0.125f; s2[ip][j].y *= 0.125f;
                ma = fmaxf(ma, s2[ip][j].x); mb = fmaxf(mb, s2[ip][j].y);
            }
            #pragma unroll
            for (int off = 8; off; off >>= 1) {
                ma = fmaxf(ma, __shfl_xor_sync(0xffffffffu, ma, off));
                mb = fmaxf(mb, __shfl_xor_sync(0xffffffffu, mb, off));
            }
            const int ra = 2*ip, rb = 2*ip + 1;
            float mna = fmaxf(m_r[ra], ma), mnb = fmaxf(m_r[rb], mb);
            float ea = __expf(m_r[ra] - mna), eb = __expf(m_r[rb] - mnb);
            float sa = 0.f, sb = 0.f;
            #pragma unroll
            for (int j = 0; j < 4; j++) {
                float pa = __expf(s2[ip][j].x - mna);
                float pb = __expf(s2[ip][j].y - mnb);
                s2[ip][j].x = pa; s2[ip][j].y = pb; sa += pa; sb += pb;
            }
            #pragma unroll
            for (int off = 8; off; off >>= 1) {
                sa += __shfl_xor_sync(0xffffffffu, sa, off);
                sb += __shfl_xor_sync(0xffffffffu, sb, off);
            }
            m_r[ra] = mna; m_r[rb] = mnb;
            l_r[ra] = l_r[ra]*ea + sa; l_r[rb] = l_r[rb]*eb + sb;
            o2[ra][0].x *= ea; o2[ra][0].y *= ea; o2[ra][1].x *= ea; o2[ra][1].y *= ea;
            o2[rb][0].x *= eb; o2[rb][0].y *= eb; o2[rb][1].x *= eb; o2[rb][1].y *= eb;
            #pragma unroll
            for (int j = 0; j < 4; j++) {
                *(float2*)&Psd[(ty*8 + ra)*132 + (tx*4 + j)*2] = make_float2(s2[ip][j].x, s2[ip][j].x);
                *(float2*)&Psd[(ty*8 + rb)*132 + (tx*4 + j)*2] = make_float2(s2[ip][j].y, s2[ip][j].y);
            }
        }
        __syncthreads();

        for (int j0 = 0; j0 < 64; j0 += 4) {
            float4 v0 = *(const float4*)&Vs[(j0+0)*68 + tx*4];
            float4 v1 = *(const float4*)&Vs[(j0+1)*68 + tx*4];
            float4 v2 = *(const float4*)&Vs[(j0+2)*68 + tx*4];
            float4 v3 = *(const float4*)&Vs[(j0+3)*68 + tx*4];
            #pragma unroll
            for (int r = 0; r < 8; r++) {
                const float* pr = &Psd[(ty*8 + r)*132 + j0*2];
                float2 p0 = *(const float2*)(pr + 0);
                float2 p1 = *(const float2*)(pr + 2);
                float2 p2 = *(const float2*)(pr + 4);
                float2 p3 = *(const float2*)(pr + 6);
                fma2(o2[r][0], p0, make_float2(v0.x, v0.y));
                fma2(o2[r][1], p0, make_float2(v0.z, v0.w));
                fma2(o2[r][0], p1, make_float2(v1.x, v1.y));
                fma2(o2[r][1], p1, make_float2(v1.z, v1.w));
                fma2(o2[r][0], p2, make_float2(v2.x, v2.y));
                fma2(o2[r][1], p2, make_float2(v2.z, v2.w));
                fma2(o2[r][0], p3, make_float2(v3.x, v3.y));
                fma2(o2[r][1], p3, make_float2(v3.z, v3.w));
            }
        }
        __syncthreads();
    }

    #pragma unroll
    for (int r = 0; r < 8; r++) {
        float inv = 1.0f / l_r[r];
        *(float4*)&Aout[(size_t)(q0 + ty*8 + r) * DMODEL + h*64 + tx*4] =
            make_float4(o2[r][0].x * inv, o2[r][0].y * inv,
                        o2[r][1].x * inv, o2[r][1].y * inv);
    }
}

extern "C" void kernel_launch(void* const* d_in, const int* in_sizes, int n_in,
                              void* d_out, int out_size)
{
    const float* q  = (const float*)d_in[0];
    const float* k  = (const float*)d_in[1];
    const float* v  = (const float*)d_in[2];
    const float* wq = (const float*)d_in[3];
    const float* wk = (const float*)d_in[4];
    const float* wv = (const float*)d_in[5];
    const float* wo = (const float*)d_in[6];
    float* out = (float*)d_out;

    float *pQ, *pKt, *pV, *pA;
    cudaGetSymbolAddress((void**)&pQ,  g_Q);
    cudaGetSymbolAddress((void**)&pKt, g_Kt);
    cudaGetSymbolAddress((void**)&pV,  g_V);
    cudaGetSymbolAddress((void**)&pA,  g_A);

    static bool attr_done = false;
    if (!attr_done) {
        cudaFuncSetAttribute(attn_kernel, cudaFuncAttributeMaxDynamicSharedMemorySize, ATT_SMEM);
        attr_done = true;
    }

    dim3 gg(16, 32), gb(256);
    gemm_xwt<<<gg, gb>>>(q, wq, pQ,  L_SEQ, DMODEL, DMODEL, 0);
    gemm_xwt<<<gg, gb>>>(k, wk, pKt, L_SEQ, DMODEL, DMODEL, 1);
    gemm_xwt<<<gg, gb>>>(v, wv, pV,  L_SEQ, DMODEL, DMODEL, 0);
    attn_kernel<<<dim3(64, 16), 128, ATT_SMEM>>>(pQ, pKt, pV, pA);
    gemm_xwt<<<gg, gb>>>(pA, wo, out, L_SEQ, DMODEL, DMODEL, 0);
}

// round 10
// speedup vs baseline: 1.4297x; 1.4297x over previous
#include <cuda_runtime.h>

#define L_SEQ  4096
#define DMODEL 1024

__device__ float g_Q [L_SEQ * DMODEL];
__device__ float g_Kt[DMODEL * L_SEQ];   // K projection TRANSPOSED [d][l]
__device__ float g_V [L_SEQ * DMODEL];
__device__ float g_A [L_SEQ * DMODEL];

__device__ __forceinline__ void fma2(float2& d, const float2 a, const float2 b) {
    unsigned long long& dd = reinterpret_cast<unsigned long long&>(d);
    const unsigned long long aa = *reinterpret_cast<const unsigned long long*>(&a);
    const unsigned long long bb = *reinterpret_cast<const unsigned long long*>(&b);
    asm("fma.rn.f32x2 %0, %1, %2, %0;" : "+l"(dd) : "l"(aa), "l"(bb));
}
__device__ __forceinline__ float2 dup2(float a) {
    float2 r;
    asm("mov.b64 %0, {%1, %1};" : "=l"(reinterpret_cast<unsigned long long&>(r)) : "f"(a));
    return r;
}

// ---------------- GEMM: Y = X(MxK) * W^T(NxK); tile 128x128, 256 thr ----------------
// thread owns rows mb+ty*8..+7 (row-paired), cols nb + tx + 16j (interleaved, j=0..7)
__global__ __launch_bounds__(256, 2)
void gemm_xwt(const float* __restrict__ X, const float* __restrict__ W,
              float* __restrict__ Y, int M, int N, int K, int transOut)
{
    __shared__ float As [16][132];   // As[k][m]
    __shared__ float Bsd[16][264];   // Bsd[k][2n] value-duplicated

    const int t  = threadIdx.x;
    const int mb = blockIdx.y * 128;
    const int nb = blockIdx.x * 128;
    const int lr = t >> 2, kg = t & 3;
    const int tx = t & 15, ty = t >> 4;

    const float* xA0 = X + (size_t)(mb + lr)      * K + kg * 4;
    const float* xA1 = X + (size_t)(mb + lr + 64) * K + kg * 4;
    const float* xB0 = W + (size_t)(nb + lr)      * K + kg * 4;
    const float* xB1 = W + (size_t)(nb + lr + 64) * K + kg * 4;

    float2 acc[4][8];
    #pragma unroll
    for (int i = 0; i < 4; i++)
        #pragma unroll
        for (int j = 0; j < 8; j++) acc[i][j] = make_float2(0.f, 0.f);

    const int nt = K / 16;
    float4 pa0 = *(const float4*)xA0;
    float4 pa1 = *(const float4*)xA1;
    float4 pb0 = *(const float4*)xB0;
    float4 pb1 = *(const float4*)xB1;

    for (int kt = 0; kt < nt; kt++) {
        __syncthreads();
        As[kg*4+0][lr]    = pa0.x; As[kg*4+1][lr]    = pa0.y;
        As[kg*4+2][lr]    = pa0.z; As[kg*4+3][lr]    = pa0.w;
        As[kg*4+0][lr+64] = pa1.x; As[kg*4+1][lr+64] = pa1.y;
        As[kg*4+2][lr+64] = pa1.z; As[kg*4+3][lr+64] = pa1.w;
        *(float2*)&Bsd[kg*4+0][2*lr]      = make_float2(pb0.x, pb0.x);
        *(float2*)&Bsd[kg*4+1][2*lr]      = make_float2(pb0.y, pb0.y);
        *(float2*)&Bsd[kg*4+2][2*lr]      = make_float2(pb0.z, pb0.z);
        *(float2*)&Bsd[kg*4+3][2*lr]      = make_float2(pb0.w, pb0.w);
        *(float2*)&Bsd[kg*4+0][2*(lr+64)] = make_float2(pb1.x, pb1.x);
        *(float2*)&Bsd[kg*4+1][2*(lr+64)] = make_float2(pb1.y, pb1.y);
        *(float2*)&Bsd[kg*4+2][2*(lr+64)] = make_float2(pb1.z, pb1.z);
        *(float2*)&Bsd[kg*4+3][2*(lr+64)] = make_float2(pb1.w, pb1.w);
        __syncthreads();
        if (kt + 1 < nt) {
            pa0 = *(const float4*)(xA0 + (kt + 1) * 16);
            pa1 = *(const float4*)(xA1 + (kt + 1) * 16);
            pb0 = *(const float4*)(xB0 + (kt + 1) * 16);
            pb1 = *(const float4*)(xB1 + (kt + 1) * 16);
        }
        #pragma unroll
        for (int k = 0; k < 16; k++) {
            float4 a0 = *(const float4*)&As[k][ty*8];
            float4 a1 = *(const float4*)&As[k][ty*8 + 4];
            float2 ap0 = make_float2(a0.x, a0.y), ap1 = make_float2(a0.z, a0.w);
            float2 ap2 = make_float2(a1.x, a1.y), ap3 = make_float2(a1.z, a1.w);
            #pragma unroll
            for (int j = 0; j < 8; j++) {
                float2 b = *(const float2*)&Bsd[k][2*tx + 32*j];   // conflict-free
                fma2(acc[0][j], ap0, b);
                fma2(acc[1][j], ap1, b);
                fma2(acc[2][j], ap2, b);
                fma2(acc[3][j], ap3, b);
            }
        }
    }

    if (!transOut) {
        #pragma unroll
        for (int ip = 0; ip < 4; ip++) {
            int m0 = mb + ty*8 + 2*ip;
            #pragma unroll
            for (int j = 0; j < 8; j++) {
                int c = nb + tx + 16*j;
                Y[(size_t)m0     * N + c] = acc[ip][j].x;
                Y[(size_t)(m0+1) * N + c] = acc[ip][j].y;
            }
        }
    } else {
        #pragma unroll
        for (int j = 0; j < 8; j++) {
            int n = nb + tx + 16*j;
            #pragma unroll
            for (int ip = 0; ip < 4; ip++)
                *(float2*)&Y[(size_t)n * M + mb + ty*8 + 2*ip] = acc[ip][j];
        }
    }
}

// ---------------- Flash attention: 128q x 64k tiles, 128 threads ----------------
// thread: 8 q-rows (ty*8+i, ty=0..15) x 8 k-cols as 4 pairs (tx*2+16jp, tx=0..7)
#define ATT_SMEM ((64*132 + 64*68 + 64*68 + 128*74) * 4)

__global__ __launch_bounds__(128)
void attn_kernel(const float* __restrict__ Qp, const float* __restrict__ Kt,
                 const float* __restrict__ Vp, float* __restrict__ Aout)
{
    extern __shared__ float sm[];
    float* Qst = sm;                 // [64][132] Q^T (scaled by 1/8): [d][r]
    float* Kst = sm + 64*132;        // [64][68]  K: [d][c]
    float* Vs  = Kst + 64*68;        // [64][68]  V: [j][dd]
    float* Ps  = Vs + 64*68;         // [128][74] P: [r][c]

    const int t  = threadIdx.x;
    const int h  = blockIdx.y;
    const int q0 = blockIdx.x * 128;
    const int tx = t & 7,  ty = t >> 3;    // compute mapping
    const int lx = t & 15, ly = t >> 4;    // fill mapping

    // load Q (128 rows x 64 d), scale by 1/sqrt(64), store transposed
    #pragma unroll
    for (int it = 0; it < 16; it++) {
        int r = ly + it*8, d0 = lx*4;
        float4 v = *(const float4*)&Qp[(size_t)(q0 + r) * DMODEL + h*64 + d0];
        Qst[(d0+0)*132 + r] = v.x * 0.125f;
        Qst[(d0+1)*132 + r] = v.y * 0.125f;
        Qst[(d0+2)*132 + r] = v.z * 0.125f;
        Qst[(d0+3)*132 + r] = v.w * 0.125f;
    }

    float2 o2[8][4];
    float  m_r[8], l_r[8];
    #pragma unroll
    for (int i = 0; i < 8; i++) {
        #pragma unroll
        for (int jp = 0; jp < 4; jp++) o2[i][jp] = make_float2(0.f, 0.f);
        m_r[i] = -1e30f; l_r[i] = 0.f;
    }
    __syncthreads();

    for (int c0 = 0; c0 < L_SEQ; c0 += 64) {
        // ---- load K chunk [64d][64c] and V chunk [64j][64dd] ----
        #pragma unroll
        for (int it = 0; it < 4; it++) {
            int a = ly + it*16, b = ly + it*16 + 8, c4 = lx*4;
            *(float4*)&Kst[a*68 + c4] = *(const float4*)&Kt[(size_t)(h*64 + a) * L_SEQ + c0 + c4];
            *(float4*)&Kst[b*68 + c4] = *(const float4*)&Kt[(size_t)(h*64 + b) * L_SEQ + c0 + c4];
            *(float4*)&Vs [a*68 + c4] = *(const float4*)&Vp[(size_t)(c0 + a) * DMODEL + h*64 + c4];
            *(float4*)&Vs [b*68 + c4] = *(const float4*)&Vp[(size_t)(c0 + b) * DMODEL + h*64 + c4];
        }
        __syncthreads();

        // ---- S = Q K^T : col-paired, A packed via mov.b64 {a,a} ----
        float2 s2[8][4];
        #pragma unroll
        for (int i = 0; i < 8; i++)
            #pragma unroll
            for (int jp = 0; jp < 4; jp++) s2[i][jp] = make_float2(0.f, 0.f);

        #pragma unroll 2
        for (int d = 0; d < 64; d++) {
            float4 a0 = *(const float4*)&Qst[d*132 + ty*8];
            float4 a1 = *(const float4*)&Qst[d*132 + ty*8 + 4];
            float2 b0 = *(const float2*)&Kst[d*68 + tx*2];
            float2 b1 = *(const float2*)&Kst[d*68 + tx*2 + 16];
            float2 b2 = *(const float2*)&Kst[d*68 + tx*2 + 32];
            float2 b3 = *(const float2*)&Kst[d*68 + tx*2 + 48];
            float av[8] = {a0.x, a0.y, a0.z, a0.w, a1.x, a1.y, a1.z, a1.w};
            #pragma unroll
            for (int i = 0; i < 8; i++) {
                float2 aa = dup2(av[i]);
                fma2(s2[i][0], aa, b0);
                fma2(s2[i][1], aa, b1);
                fma2(s2[i][2], aa, b2);
                fma2(s2[i][3], aa, b3);
            }
        }

        // ---- online softmax per row (shfl over 8-lane tx group) ----
        #pragma unroll
        for (int i = 0; i < 8; i++) {
            float2 mx = make_float2(fmaxf(s2[i][0].x, s2[i][1].x), fmaxf(s2[i][0].y, s2[i][1].y));
            mx.x = fmaxf(mx.x, fmaxf(s2[i][2].x, s2[i][3].x));
            mx.y = fmaxf(mx.y, fmaxf(s2[i][2].y, s2[i][3].y));
            float m = fmaxf(mx.x, mx.y);
            m = fmaxf(m, __shfl_xor_sync(0xffffffffu, m, 1));
            m = fmaxf(m, __shfl_xor_sync(0xffffffffu, m, 2));
            m = fmaxf(m, __shfl_xor_sync(0xffffffffu, m, 4));
            float mn = fmaxf(m_r[i], m);
            float e  = __expf(m_r[i] - mn);
            float s  = 0.f;
            #pragma unroll
            for (int jp = 0; jp < 4; jp++) {
                s2[i][jp].x = __expf(s2[i][jp].x - mn);
                s2[i][jp].y = __expf(s2[i][jp].y - mn);
                s += s2[i][jp].x + s2[i][jp].y;
            }
            s += __shfl_xor_sync(0xffffffffu, s, 1);
            s += __shfl_xor_sync(0xffffffffu, s, 2);
            s += __shfl_xor_sync(0xffffffffu, s, 4);
            m_r[i] = mn;
            l_r[i] = l_r[i]*e + s;
            #pragma unroll
            for (int jp = 0; jp < 4; jp++) { o2[i][jp].x *= e; o2[i][jp].y *= e; }
            int row = ty*8 + i;
            *(float2*)&Ps[row*74 + tx*2]      = s2[i][0];
            *(float2*)&Ps[row*74 + tx*2 + 16] = s2[i][1];
            *(float2*)&Ps[row*74 + tx*2 + 32] = s2[i][2];
            *(float2*)&Ps[row*74 + tx*2 + 48] = s2[i][3];
        }
        __syncthreads();

        // ---- O += P V : 2 keys per iteration ----
        #pragma unroll 2
        for (int j = 0; j < 64; j += 2) {
            float2 b00 = *(const float2*)&Vs[j*68 + tx*2];
            float2 b01 = *(const float2*)&Vs[j*68 + tx*2 + 16];
            float2 b02 = *(const float2*)&Vs[j*68 + tx*2 + 32];
            float2 b03 = *(const float2*)&Vs[j*68 + tx*2 + 48];
            float2 b10 = *(const float2*)&Vs[(j+1)*68 + tx*2];
            float2 b11 = *(const float2*)&Vs[(j+1)*68 + tx*2 + 16];
            float2 b12 = *(const float2*)&Vs[(j+1)*68 + tx*2 + 32];
            float2 b13 = *(const float2*)&Vs[(j+1)*68 + tx*2 + 48];
            #pragma unroll
            for (int i = 0; i < 8; i++) {
                float2 pj = *(const float2*)&Ps[(ty*8 + i)*74 + j];
                float2 p0 = dup2(pj.x), p1 = dup2(pj.y);
                fma2(o2[i][0], p0, b00); fma2(o2[i][1], p0, b01);
                fma2(o2[i][2], p0, b02); fma2(o2[i][3], p0, b03);
                fma2(o2[i][0], p1, b10); fma2(o2[i][1], p1, b11);
                fma2(o2[i][2], p1, b12); fma2(o2[i][3], p1, b13);
            }
        }
        __syncthreads();
    }

    // ---- normalize + write ----
    #pragma unroll
    for (int i = 0; i < 8; i++) {
        float inv = 1.0f / l_r[i];
        size_t base = (size_t)(q0 + ty*8 + i) * DMODEL + h*64 + tx*2;
        *(float2*)&Aout[base]      = make_float2(o2[i][0].x*inv, o2[i][0].y*inv);
        *(float2*)&Aout[base + 16] = make_float2(o2[i][1].x*inv, o2[i][1].y*inv);
        *(float2*)&Aout[base + 32] = make_float2(o2[i][2].x*inv, o2[i][2].y*inv);
        *(float2*)&Aout[base + 48] = make_float2(o2[i][3].x*inv, o2[i][3].y*inv);
    }
}

extern "C" void kernel_launch(void* const* d_in, const int* in_sizes, int n_in,
                              void* d_out, int out_size)
{
    const float* q  = (const float*)d_in[0];
    const float* k  = (const float*)d_in[1];
    const float* v  = (const float*)d_in[2];
    const float* wq = (const float*)d_in[3];
    const float* wk = (const float*)d_in[4];
    const float* wv = (const float*)d_in[5];
    const float* wo = (const float*)d_in[6];
    float* out = (float*)d_out;

    float *pQ, *pKt, *pV, *pA;
    cudaGetSymbolAddress((void**)&pQ,  g_Q);
    cudaGetSymbolAddress((void**)&pKt, g_Kt);
    cudaGetSymbolAddress((void**)&pV,  g_V);
    cudaGetSymbolAddress((void**)&pA,  g_A);

    static bool attr_done = false;
    if (!attr_done) {
        cudaFuncSetAttribute(attn_kernel, cudaFuncAttributeMaxDynamicSharedMemorySize, ATT_SMEM);
        attr_done = true;
    }

    dim3 gg(8, 32), gb(256);
    gemm_xwt<<<gg, gb>>>(q, wq, pQ,  L_SEQ, DMODEL, DMODEL, 0);
    gemm_xwt<<<gg, gb>>>(k, wk, pKt, L_SEQ, DMODEL, DMODEL, 1);
    gemm_xwt<<<gg, gb>>>(v, wv, pV,  L_SEQ, DMODEL, DMODEL, 0);
    attn_kernel<<<dim3(32, 16), 128, ATT_SMEM>>>(pQ, pKt, pV, pA);
    gemm_xwt<<<gg, gb>>>(pA, wo, out, L_SEQ, DMODEL, DMODEL, 0);
}

// round 11
// speedup vs baseline: 1.4791x; 1.0346x over previous
#include <cuda_runtime.h>

#define L_SEQ  4096
#define DMODEL 1024

__device__ float g_Q [L_SEQ * DMODEL];
__device__ float g_Kt[DMODEL * L_SEQ];   // K projection TRANSPOSED [d][l]
__device__ float g_V [L_SEQ * DMODEL];
__device__ float g_A [L_SEQ * DMODEL];

__device__ __forceinline__ void fma2(float2& d, const float2 a, const float2 b) {
    unsigned long long& dd = reinterpret_cast<unsigned long long&>(d);
    const unsigned long long aa = *reinterpret_cast<const unsigned long long*>(&a);
    const unsigned long long bb = *reinterpret_cast<const unsigned long long*>(&b);
    asm("fma.rn.f32x2 %0, %1, %2, %0;" : "+l"(dd) : "l"(aa), "l"(bb));
}
__device__ __forceinline__ float2 dup2(float a) {
    float2 r;
    asm("mov.b64 %0, {%1, %1};" : "=l"(reinterpret_cast<unsigned long long&>(r)) : "f"(a));
    return r;
}

// ---------------- GEMM: Y = X(MxK) * W^T(NxK); tile 128x128, 256 thr ----------------
__global__ __launch_bounds__(256, 2)
void gemm_xwt(const float* __restrict__ X, const float* __restrict__ W,
              float* __restrict__ Y, int M, int N, int K, int transOut)
{
    __shared__ float As [16][132];   // As[k][m]
    __shared__ float Bsd[16][264];   // Bsd[k][2n] value-duplicated

    const int t  = threadIdx.x;
    const int mb = blockIdx.y * 128;
    const int nb = blockIdx.x * 128;
    const int lr = t >> 2, kg = t & 3;
    const int tx = t & 15, ty = t >> 4;

    const float* xA0 = X + (size_t)(mb + lr)      * K + kg * 4;
    const float* xA1 = X + (size_t)(mb + lr + 64) * K + kg * 4;
    const float* xB0 = W + (size_t)(nb + lr)      * K + kg * 4;
    const float* xB1 = W + (size_t)(nb + lr + 64) * K + kg * 4;

    float2 acc[4][8];
    #pragma unroll
    for (int i = 0; i < 4; i++)
        #pragma unroll
        for (int j = 0; j < 8; j++) acc[i][j] = make_float2(0.f, 0.f);

    const int nt = K / 16;
    float4 pa0 = *(const float4*)xA0;
    float4 pa1 = *(const float4*)xA1;
    float4 pb0 = *(const float4*)xB0;
    float4 pb1 = *(const float4*)xB1;

    for (int kt = 0; kt < nt; kt++) {
        __syncthreads();
        As[kg*4+0][lr]    = pa0.x; As[kg*4+1][lr]    = pa0.y;
        As[kg*4+2][lr]    = pa0.z; As[kg*4+3][lr]    = pa0.w;
        As[kg*4+0][lr+64] = pa1.x; As[kg*4+1][lr+64] = pa1.y;
        As[kg*4+2][lr+64] = pa1.z; As[kg*4+3][lr+64] = pa1.w;
        *(float2*)&Bsd[kg*4+0][2*lr]      = make_float2(pb0.x, pb0.x);
        *(float2*)&Bsd[kg*4+1][2*lr]      = make_float2(pb0.y, pb0.y);
        *(float2*)&Bsd[kg*4+2][2*lr]      = make_float2(pb0.z, pb0.z);
        *(float2*)&Bsd[kg*4+3][2*lr]      = make_float2(pb0.w, pb0.w);
        *(float2*)&Bsd[kg*4+0][2*(lr+64)] = make_float2(pb1.x, pb1.x);
        *(float2*)&Bsd[kg*4+1][2*(lr+64)] = make_float2(pb1.y, pb1.y);
        *(float2*)&Bsd[kg*4+2][2*(lr+64)] = make_float2(pb1.z, pb1.z);
        *(float2*)&Bsd[kg*4+3][2*(lr+64)] = make_float2(pb1.w, pb1.w);
        __syncthreads();
        if (kt + 1 < nt) {
            pa0 = *(const float4*)(xA0 + (kt + 1) * 16);
            pa1 = *(const float4*)(xA1 + (kt + 1) * 16);
            pb0 = *(const float4*)(xB0 + (kt + 1) * 16);
            pb1 = *(const float4*)(xB1 + (kt + 1) * 16);
        }
        #pragma unroll
        for (int k = 0; k < 16; k++) {
            float4 a0 = *(const float4*)&As[k][ty*8];
            float4 a1 = *(const float4*)&As[k][ty*8 + 4];
            float2 ap0 = make_float2(a0.x, a0.y), ap1 = make_float2(a0.z, a0.w);
            float2 ap2 = make_float2(a1.x, a1.y), ap3 = make_float2(a1.z, a1.w);
            #pragma unroll
            for (int j = 0; j < 8; j++) {
                float2 b = *(const float2*)&Bsd[k][2*tx + 32*j];
                fma2(acc[0][j], ap0, b);
                fma2(acc[1][j], ap1, b);
                fma2(acc[2][j], ap2, b);
                fma2(acc[3][j], ap3, b);
            }
        }
    }

    if (!transOut) {
        #pragma unroll
        for (int ip = 0; ip < 4; ip++) {
            int m0 = mb + ty*8 + 2*ip;
            #pragma unroll
            for (int j = 0; j < 8; j++) {
                int c = nb + tx + 16*j;
                Y[(size_t)m0     * N + c] = acc[ip][j].x;
                Y[(size_t)(m0+1) * N + c] = acc[ip][j].y;
            }
        }
    } else {
        #pragma unroll
        for (int j = 0; j < 8; j++) {
            int n = nb + tx + 16*j;
            #pragma unroll
            for (int ip = 0; ip < 4; ip++)
                *(float2*)&Y[(size_t)n * M + mb + ty*8 + 2*ip] = acc[ip][j];
        }
    }
}

// ---------------- Flash attention: 128q x 64k tiles, 256 threads ----------------
// thread: 4 q-rows (ty*4+i, ty=t>>3, 0..31) x 8 k-cols as 4 pairs (tx*2+16jp, tx=t&7)
// warp w owns P rows [16w, 16w+16) exclusively -> P exchange is intra-warp (__syncwarp).
#define ATT_SMEM ((64*132 + 64*68 + 64*68 + 128*74) * 4)

__global__ __launch_bounds__(256, 2)
void attn_kernel(const float* __restrict__ Qp, const float* __restrict__ Kt,
                 const float* __restrict__ Vp, float* __restrict__ Aout)
{
    extern __shared__ float sm[];
    float* Qst = sm;                 // [64][132] Q^T (scaled by 1/8): [d][r]
    float* Kst = sm + 64*132;        // [64][68]  K: [d][c]
    float* Vs  = Kst + 64*68;        // [64][68]  V: [j][dd]
    float* Ps  = Vs + 64*68;         // [128][74] P: [r][c]

    const int t  = threadIdx.x;
    const int h  = blockIdx.y;
    const int q0 = blockIdx.x * 128;
    const int tx = t & 7,  ty = t >> 3;    // compute mapping: 4 rows x 8 cols
    const int lx = t & 15, ly = t >> 4;    // fill mapping (16x16)

    // load Q (128 rows x 64 d), scale by 1/sqrt(64), store transposed
    #pragma unroll
    for (int it = 0; it < 8; it++) {
        int r = ly + it*16, d0 = lx*4;
        float4 v = *(const float4*)&Qp[(size_t)(q0 + r) * DMODEL + h*64 + d0];
        Qst[(d0+0)*132 + r] = v.x * 0.125f;
        Qst[(d0+1)*132 + r] = v.y * 0.125f;
        Qst[(d0+2)*132 + r] = v.z * 0.125f;
        Qst[(d0+3)*132 + r] = v.w * 0.125f;
    }

    float2 o2[4][4];
    float  m_r[4], l_r[4];
    #pragma unroll
    for (int i = 0; i < 4; i++) {
        #pragma unroll
        for (int jp = 0; jp < 4; jp++) o2[i][jp] = make_float2(0.f, 0.f);
        m_r[i] = -1e30f; l_r[i] = 0.f;
    }

    for (int c0 = 0; c0 < L_SEQ; c0 += 64) {
        // ---- load K chunk [64d][64c] and V chunk [64j][64dd] ----
        __syncthreads();   // prev PV done reading Kst/Vs
        #pragma unroll
        for (int it = 0; it < 4; it++) {
            int d = ly + it*16, c4 = lx*4;
            *(float4*)&Kst[d*68 + c4] = *(const float4*)&Kt[(size_t)(h*64 + d) * L_SEQ + c0 + c4];
            *(float4*)&Vs [d*68 + c4] = *(const float4*)&Vp[(size_t)(c0 + d) * DMODEL + h*64 + c4];
        }
        __syncthreads();

        // ---- S = Q K^T ----
        float2 s2[4][4];
        #pragma unroll
        for (int i = 0; i < 4; i++)
            #pragma unroll
            for (int jp = 0; jp < 4; jp++) s2[i][jp] = make_float2(0.f, 0.f);

        #pragma unroll 4
        for (int d = 0; d < 64; d++) {
            float4 a  = *(const float4*)&Qst[d*132 + ty*4];
            float2 b0 = *(const float2*)&Kst[d*68 + tx*2];
            float2 b1 = *(const float2*)&Kst[d*68 + tx*2 + 16];
            float2 b2 = *(const float2*)&Kst[d*68 + tx*2 + 32];
            float2 b3 = *(const float2*)&Kst[d*68 + tx*2 + 48];
            float av[4] = {a.x, a.y, a.z, a.w};
            #pragma unroll
            for (int i = 0; i < 4; i++) {
                float2 aa = dup2(av[i]);
                fma2(s2[i][0], aa, b0);
                fma2(s2[i][1], aa, b1);
                fma2(s2[i][2], aa, b2);
                fma2(s2[i][3], aa, b3);
            }
        }

        // ---- online softmax per row (shfl over 8-lane tx group) ----
        #pragma unroll
        for (int i = 0; i < 4; i++) {
            float2 mx = make_float2(fmaxf(s2[i][0].x, s2[i][1].x), fmaxf(s2[i][0].y, s2[i][1].y));
            mx.x = fmaxf(mx.x, fmaxf(s2[i][2].x, s2[i][3].x));
            mx.y = fmaxf(mx.y, fmaxf(s2[i][2].y, s2[i][3].y));
            float m = fmaxf(mx.x, mx.y);
            m = fmaxf(m, __shfl_xor_sync(0xffffffffu, m, 1));
            m = fmaxf(m, __shfl_xor_sync(0xffffffffu, m, 2));
            m = fmaxf(m, __shfl_xor_sync(0xffffffffu, m, 4));
            float mn = fmaxf(m_r[i], m);
            float e  = __expf(m_r[i] - mn);
            float s  = 0.f;
            #pragma unroll
            for (int jp = 0; jp < 4; jp++) {
                s2[i][jp].x = __expf(s2[i][jp].x - mn);
                s2[i][jp].y = __expf(s2[i][jp].y - mn);
                s += s2[i][jp].x + s2[i][jp].y;
            }
            s += __shfl_xor_sync(0xffffffffu, s, 1);
            s += __shfl_xor_sync(0xffffffffu, s, 2);
            s += __shfl_xor_sync(0xffffffffu, s, 4);
            m_r[i] = mn;
            l_r[i] = l_r[i]*e + s;
            #pragma unroll
            for (int jp = 0; jp < 4; jp++) { o2[i][jp].x *= e; o2[i][jp].y *= e; }
            int row = ty*4 + i;
            *(float2*)&Ps[row*74 + tx*2]      = s2[i][0];
            *(float2*)&Ps[row*74 + tx*2 + 16] = s2[i][1];
            *(float2*)&Ps[row*74 + tx*2 + 32] = s2[i][2];
            *(float2*)&Ps[row*74 + tx*2 + 48] = s2[i][3];
        }
        __syncwarp();   // P rows are warp-private: no block barrier needed

        // ---- O += P V : 2 keys per iteration ----
        #pragma unroll 2
        for (int j = 0; j < 64; j += 2) {
            float2 b00 = *(const float2*)&Vs[j*68 + tx*2];
            float2 b01 = *(const float2*)&Vs[j*68 + tx*2 + 16];
            float2 b02 = *(const float2*)&Vs[j*68 + tx*2 + 32];
            float2 b03 = *(const float2*)&Vs[j*68 + tx*2 + 48];
            float2 b10 = *(const float2*)&Vs[(j+1)*68 + tx*2];
            float2 b11 = *(const float2*)&Vs[(j+1)*68 + tx*2 + 16];
            float2 b12 = *(const float2*)&Vs[(j+1)*68 + tx*2 + 32];
            float2 b13 = *(const float2*)&Vs[(j+1)*68 + tx*2 + 48];
            #pragma unroll
            for (int i = 0; i < 4; i++) {
                float2 pj = *(const float2*)&Ps[(ty*4 + i)*74 + j];
                float2 p0 = dup2(pj.x), p1 = dup2(pj.y);
                fma2(o2[i][0], p0, b00); fma2(o2[i][1], p0, b01);
                fma2(o2[i][2], p0, b02); fma2(o2[i][3], p0, b03);
                fma2(o2[i][0], p1, b10); fma2(o2[i][1], p1, b11);
                fma2(o2[i][2], p1, b12); fma2(o2[i][3], p1, b13);
            }
        }
    }

    // ---- normalize + write ----
    #pragma unroll
    for (int i = 0; i < 4; i++) {
        float inv = 1.0f / l_r[i];
        size_t base = (size_t)(q0 + ty*4 + i) * DMODEL + h*64 + tx*2;
        *(float2*)&Aout[base]      = make_float2(o2[i][0].x*inv, o2[i][0].y*inv);
        *(float2*)&Aout[base + 16] = make_float2(o2[i][1].x*inv, o2[i][1].y*inv);
        *(float2*)&Aout[base + 32] = make_float2(o2[i][2].x*inv, o2[i][2].y*inv);
        *(float2*)&Aout[base + 48] = make_float2(o2[i][3].x*inv, o2[i][3].y*inv);
    }
}

extern "C" void kernel_launch(void* const* d_in, const int* in_sizes, int n_in,
                              void* d_out, int out_size)
{
    const float* q  = (const float*)d_in[0];
    const float* k  = (const float*)d_in[1];
    const float* v  = (const float*)d_in[2];
    const float* wq = (const float*)d_in[3];
    const float* wk = (const float*)d_in[4];
    const float* wv = (const float*)d_in[5];
    const float* wo = (const float*)d_in[6];
    float* out = (float*)d_out;

    float *pQ, *pKt, *pV, *pA;
    cudaGetSymbolAddress((void**)&pQ,  g_Q);
    cudaGetSymbolAddress((void**)&pKt, g_Kt);
    cudaGetSymbolAddress((void**)&pV,  g_V);
    cudaGetSymbolAddress((void**)&pA,  g_A);

    static bool attr_done = false;
    if (!attr_done) {
        cudaFuncSetAttribute(attn_kernel, cudaFuncAttributeMaxDynamicSharedMemorySize, ATT_SMEM);
        attr_done = true;
    }

    dim3 gg(8, 32), gb(256);
    gemm_xwt<<<gg, gb>>>(q, wq, pQ,  L_SEQ, DMODEL, DMODEL, 0);
    gemm_xwt<<<gg, gb>>>(k, wk, pKt, L_SEQ, DMODEL, DMODEL, 1);
    gemm_xwt<<<gg, gb>>>(v, wv, pV,  L_SEQ, DMODEL, DMODEL, 0);
    attn_kernel<<<dim3(32, 16), 256, ATT_SMEM>>>(pQ, pKt, pV, pA);
    gemm_xwt<<<gg, gb>>>(pA, wo, out, L_SEQ, DMODEL, DMODEL, 0);
}